// round 3
// baseline (speedup 1.0000x reference)
#include <cuda_runtime.h>
#include <math.h>

#define NB   8
#define CDIM 256
#define CKD  64
#define NN   4096

// Scratch (allocation-free rule: __device__ globals)
__device__ float g_Q[NB * CKD * NN];   // 8 MB
__device__ float g_K[NB * CKD * NN];   // 8 MB
__device__ float g_V[NB * CDIM * NN];  // 33.5 MB
__device__ float g_O[NB * CDIM * NN];  // 33.5 MB

// ---------------------------------------------------------------------------
// Generic projection GEMM: out[b, o, n] = sum_c W[o,c] * X[b,c,n] + bias[o]
// Grid: (NN/128, R/64, NB), 256 threads. Thread computes 4(o) x 8(n).
// ---------------------------------------------------------------------------
__global__ __launch_bounds__(256) void proj_kernel(
    const float* __restrict__ W, const float* __restrict__ bias,
    const float* __restrict__ X, float* __restrict__ out, int R)
{
    __shared__ float Xs[32][128];
    __shared__ float Ws[32][65];   // [cc][o], odd stride -> conflict-free scalar reads

    const int b  = blockIdx.z;
    const int o0 = blockIdx.y * 64;
    const int n0 = blockIdx.x * 128;
    const int tid = threadIdx.x;
    const int tx = tid & 15;       // n group
    const int ty = tid >> 4;       // o group

    const float* Xb = X + (size_t)b * CDIM * NN;

    float acc[4][8];
#pragma unroll
    for (int i = 0; i < 4; ++i)
#pragma unroll
        for (int j = 0; j < 8; ++j) acc[i][j] = 0.f;

    for (int c0 = 0; c0 < CDIM; c0 += 32) {
        // load X tile 32x128 (float4, coalesced)
#pragma unroll
        for (int r = 0; r < 4; ++r) {
            int row = (tid >> 5) + r * 8;
            int col = (tid & 31) * 4;
            *(float4*)&Xs[row][col] =
                *(const float4*)&Xb[(size_t)(c0 + row) * NN + n0 + col];
        }
        // load W tile 64x32 -> Ws[cc][o]
#pragma unroll
        for (int r = 0; r < 8; ++r) {
            int idx = tid + r * 256;
            int o = idx >> 5, cc = idx & 31;
            Ws[cc][o] = W[(size_t)(o0 + o) * CDIM + c0 + cc];
        }
        __syncthreads();

#pragma unroll
        for (int cc = 0; cc < 32; ++cc) {
            float w0 = Ws[cc][ty * 4 + 0];
            float w1 = Ws[cc][ty * 4 + 1];
            float w2 = Ws[cc][ty * 4 + 2];
            float w3 = Ws[cc][ty * 4 + 3];
            float4 xa = *(float4*)&Xs[cc][tx * 8];
            float4 xb = *(float4*)&Xs[cc][tx * 8 + 4];
            float xv[8] = {xa.x, xa.y, xa.z, xa.w, xb.x, xb.y, xb.z, xb.w};
#pragma unroll
            for (int j = 0; j < 8; ++j) {
                acc[0][j] = fmaf(w0, xv[j], acc[0][j]);
                acc[1][j] = fmaf(w1, xv[j], acc[1][j]);
                acc[2][j] = fmaf(w2, xv[j], acc[2][j]);
                acc[3][j] = fmaf(w3, xv[j], acc[3][j]);
            }
        }
        __syncthreads();
    }

#pragma unroll
    for (int i = 0; i < 4; ++i) {
        int o = o0 + ty * 4 + i;
        float bi = bias[o];
        float4 r0 = {acc[i][0] + bi, acc[i][1] + bi, acc[i][2] + bi, acc[i][3] + bi};
        float4 r1 = {acc[i][4] + bi, acc[i][5] + bi, acc[i][6] + bi, acc[i][7] + bi};
        float* op = out + ((size_t)b * R + o) * NN + n0 + tx * 8;
        *(float4*)&op[0] = r0;
        *(float4*)&op[4] = r1;
    }
}

// ---------------------------------------------------------------------------
// Fused attention: per CTA (b, 128 j-cols). Loop over i in tiles of 64:
//   S[i,j] = sum_d Q[d,i]*K[d,j];  P = elu(S)/N;  O[c,j] += V[c,i]*P[i,j]
// energy NEVER touches global memory.
// smem: Kj 64x128 (32KB) + Qi 64x64 (16KB) + P 64x128 (32KB) + Vs 256x64 (64KB)
// ---------------------------------------------------------------------------
__device__ __forceinline__ float elu_scaled(float x) {
    const float invN = 1.0f / 4096.0f;
    return (x > 0.f ? x : (expf(x) - 1.f)) * invN;
}

__global__ __launch_bounds__(512, 1) void attn_kernel()
{
    extern __shared__ float sm[];
    float* Kj = sm;                    // [64][128]
    float* Qi = Kj + 64 * 128;         // [64][64]
    float* Ps = Qi + 64 * 64;          // [64][128]
    float* Vs = Ps + 64 * 128;         // [256][64]

    const int b   = blockIdx.y;
    const int j0g = blockIdx.x * 128;
    const int tid = threadIdx.x;

    const float* Qb = g_Q + (size_t)b * CKD * NN;
    const float* Kb = g_K + (size_t)b * CKD * NN;
    const float* Vb = g_V + (size_t)b * CDIM * NN;

    // --- load K tile once (64 x 128) ---
#pragma unroll
    for (int r = 0; r < 4; ++r) {
        int idx4 = tid + r * 512;
        int d = idx4 >> 5, jj = (idx4 & 31) * 4;
        *(float4*)&Kj[d * 128 + jj] = *(const float4*)&Kb[(size_t)d * NN + j0g + jj];
    }

    // S-phase mapping: 16(i-groups) x 32(j-groups), micro 4x4
    const int iS0 = (tid >> 5) * 4;
    const int jS0 = (tid & 31) * 4;
    // O-phase mapping: 32(c-groups) x 16(j-groups), micro 8x8
    const int c0  = (tid >> 4) * 8;
    const int jO0 = (tid & 15) * 8;

    float oacc[8][8];
#pragma unroll
    for (int k = 0; k < 8; ++k)
#pragma unroll
        for (int j = 0; j < 8; ++j) oacc[k][j] = 0.f;

    for (int it = 0; it < 64; ++it) {
        const int i0g = it * 64;
        __syncthreads();   // previous O-phase done reading Ps/Vs

        // load Q tile 64x64
#pragma unroll
        for (int r = 0; r < 2; ++r) {
            int idx4 = tid + r * 512;
            int d = idx4 >> 4, ii = (idx4 & 15) * 4;
            *(float4*)&Qi[d * 64 + ii] = *(const float4*)&Qb[(size_t)d * NN + i0g + ii];
        }
        // load V tile 256x64
#pragma unroll
        for (int r = 0; r < 8; ++r) {
            int idx4 = tid + r * 512;
            int c = idx4 >> 4, ii = (idx4 & 15) * 4;
            *(float4*)&Vs[c * 64 + ii] = *(const float4*)&Vb[(size_t)c * NN + i0g + ii];
        }
        __syncthreads();

        // --- S = Q_i^T K_j (64x128, k-dim 64), thread: 4i x 4j ---
        float s[4][4];
#pragma unroll
        for (int a = 0; a < 4; ++a)
#pragma unroll
            for (int bb = 0; bb < 4; ++bb) s[a][bb] = 0.f;

#pragma unroll
        for (int d = 0; d < 64; ++d) {
            float4 q4 = *(float4*)&Qi[d * 64 + iS0];
            float4 k4 = *(float4*)&Kj[d * 128 + jS0];
            float qv[4] = {q4.x, q4.y, q4.z, q4.w};
            float kv[4] = {k4.x, k4.y, k4.z, k4.w};
#pragma unroll
            for (int a = 0; a < 4; ++a)
#pragma unroll
                for (int bb = 0; bb < 4; ++bb)
                    s[a][bb] = fmaf(qv[a], kv[bb], s[a][bb]);
        }

        // --- P = elu(S)/N into smem ---
#pragma unroll
        for (int a = 0; a < 4; ++a) {
            float4 p;
            p.x = elu_scaled(s[a][0]);
            p.y = elu_scaled(s[a][1]);
            p.z = elu_scaled(s[a][2]);
            p.w = elu_scaled(s[a][3]);
            *(float4*)&Ps[(iS0 + a) * 128 + jS0] = p;
        }
        __syncthreads();

        // --- O[c,j] += V[c,i] * P[i,j], thread: 8c x 8j ---
#pragma unroll 8
        for (int i = 0; i < 64; ++i) {
            float4 p0 = *(float4*)&Ps[i * 128 + jO0];
            float4 p1 = *(float4*)&Ps[i * 128 + jO0 + 4];
            float pv[8] = {p0.x, p0.y, p0.z, p0.w, p1.x, p1.y, p1.z, p1.w};
#pragma unroll
            for (int k = 0; k < 8; ++k) {
                float v = Vs[(c0 + k) * 64 + i];
#pragma unroll
                for (int j = 0; j < 8; ++j)
                    oacc[k][j] = fmaf(v, pv[j], oacc[k][j]);
            }
        }
    }

    // --- store O tile to global scratch ---
    float* Ob = g_O + (size_t)b * CDIM * NN;
#pragma unroll
    for (int k = 0; k < 8; ++k) {
        float4 r0 = {oacc[k][0], oacc[k][1], oacc[k][2], oacc[k][3]};
        float4 r1 = {oacc[k][4], oacc[k][5], oacc[k][6], oacc[k][7]};
        float* op = Ob + (size_t)(c0 + k) * NN + j0g + jO0;
        *(float4*)&op[0] = r0;
        *(float4*)&op[4] = r1;
    }
}

// ---------------------------------------------------------------------------
extern "C" void kernel_launch(void* const* d_in, const int* in_sizes, int n_in,
                              void* d_out, int out_size)
{
    const float* x  = (const float*)d_in[0];
    const float* wq = (const float*)d_in[1];
    const float* bq = (const float*)d_in[2];
    const float* wk = (const float*)d_in[3];
    const float* bk = (const float*)d_in[4];
    const float* wv = (const float*)d_in[5];
    const float* bv = (const float*)d_in[6];
    const float* wg = (const float*)d_in[7];
    const float* bg = (const float*)d_in[8];
    float* out = (float*)d_out;

    float *Qp, *Kp, *Vp, *Op;
    cudaGetSymbolAddress((void**)&Qp, g_Q);
    cudaGetSymbolAddress((void**)&Kp, g_K);
    cudaGetSymbolAddress((void**)&Vp, g_V);
    cudaGetSymbolAddress((void**)&Op, g_O);

    const int smem_attn = (64 * 128 + 64 * 64 + 64 * 128 + 256 * 64) * 4; // 147456
    cudaFuncSetAttribute(attn_kernel, cudaFuncAttributeMaxDynamicSharedMemorySize,
                         smem_attn);

    // QKV projections
    proj_kernel<<<dim3(NN / 128, CKD  / 64, NB), 256>>>(wq, bq, x, Qp, CKD);
    proj_kernel<<<dim3(NN / 128, CKD  / 64, NB), 256>>>(wk, bk, x, Kp, CKD);
    proj_kernel<<<dim3(NN / 128, CDIM / 64, NB), 256>>>(wv, bv, x, Vp, CDIM);

    // Fused attention (energy never materialized)
    attn_kernel<<<dim3(NN / 128, NB), 512, smem_attn>>>();

    // Final 1x1 conv (wg)
    proj_kernel<<<dim3(NN / 128, CDIM / 64, NB), 256>>>(wg, bg, Op, out, CDIM);
}

// round 5
// speedup vs baseline: 2.0854x; 2.0854x over previous
#include <cuda_runtime.h>
#include <cuda_bf16.h>
#include <math.h>
#include <stdint.h>

#define NB   8
#define CDIM 256
#define CKD  64
#define NN   4096

// Scratch (allocation-free rule: __device__ globals)
__device__ float g_Q[NB * CKD * NN];   // 8 MB
__device__ float g_K[NB * CKD * NN];   // 8 MB
__device__ float g_V[NB * CDIM * NN];  // 33.5 MB
__device__ float g_O[NB * CDIM * NN];  // 33.5 MB

// ---------------------------------------------------------------------------
// Generic projection GEMM: out[b, o, n] = sum_c W[o,c] * X[b,c,n] + bias[o]
// ---------------------------------------------------------------------------
__global__ __launch_bounds__(256) void proj_kernel(
    const float* __restrict__ W, const float* __restrict__ bias,
    const float* __restrict__ X, float* __restrict__ out, int R)
{
    __shared__ float Xs[32][128];
    __shared__ float Ws[32][65];

    const int b  = blockIdx.z;
    const int o0 = blockIdx.y * 64;
    const int n0 = blockIdx.x * 128;
    const int tid = threadIdx.x;
    const int tx = tid & 15;
    const int ty = tid >> 4;

    const float* Xb = X + (size_t)b * CDIM * NN;

    float acc[4][8];
#pragma unroll
    for (int i = 0; i < 4; ++i)
#pragma unroll
        for (int j = 0; j < 8; ++j) acc[i][j] = 0.f;

    for (int c0 = 0; c0 < CDIM; c0 += 32) {
#pragma unroll
        for (int r = 0; r < 4; ++r) {
            int row = (tid >> 5) + r * 8;
            int col = (tid & 31) * 4;
            *(float4*)&Xs[row][col] =
                *(const float4*)&Xb[(size_t)(c0 + row) * NN + n0 + col];
        }
#pragma unroll
        for (int r = 0; r < 8; ++r) {
            int idx = tid + r * 256;
            int o = idx >> 5, cc = idx & 31;
            Ws[cc][o] = W[(size_t)(o0 + o) * CDIM + c0 + cc];
        }
        __syncthreads();

#pragma unroll
        for (int cc = 0; cc < 32; ++cc) {
            float w0 = Ws[cc][ty * 4 + 0];
            float w1 = Ws[cc][ty * 4 + 1];
            float w2 = Ws[cc][ty * 4 + 2];
            float w3 = Ws[cc][ty * 4 + 3];
            float4 xa = *(float4*)&Xs[cc][tx * 8];
            float4 xb = *(float4*)&Xs[cc][tx * 8 + 4];
            float xv[8] = {xa.x, xa.y, xa.z, xa.w, xb.x, xb.y, xb.z, xb.w};
#pragma unroll
            for (int j = 0; j < 8; ++j) {
                acc[0][j] = fmaf(w0, xv[j], acc[0][j]);
                acc[1][j] = fmaf(w1, xv[j], acc[1][j]);
                acc[2][j] = fmaf(w2, xv[j], acc[2][j]);
                acc[3][j] = fmaf(w3, xv[j], acc[3][j]);
            }
        }
        __syncthreads();
    }

#pragma unroll
    for (int i = 0; i < 4; ++i) {
        int o = o0 + ty * 4 + i;
        float bi = bias[o];
        float4 r0 = {acc[i][0] + bi, acc[i][1] + bi, acc[i][2] + bi, acc[i][3] + bi};
        float4 r1 = {acc[i][4] + bi, acc[i][5] + bi, acc[i][6] + bi, acc[i][7] + bi};
        float* op = out + ((size_t)b * R + o) * NN + n0 + tx * 8;
        *(float4*)&op[0] = r0;
        *(float4*)&op[4] = r1;
    }
}

// ---------------------------------------------------------------------------
// Fused attention: explicit mma.sync m16n8k16 bf16 with 2-term split
// (x = xh + xl, product via Ah*Bh + Ah*Bl + Al*Bh; error ~2^-18).
// Per CTA: (b, 128 j). i tiled by 64. energy never leaves smem.
// ---------------------------------------------------------------------------
#define QLDb 72
#define KLDb 136
#define PLDb 136
#define VLDb 72

__device__ __forceinline__ float elu_scaled(float x) {
    const float invN = 1.0f / 4096.0f;
    return (x > 0.f ? x : (expf(x) - 1.f)) * invN;
}

__device__ __forceinline__ void split2(float x, __nv_bfloat16& h, __nv_bfloat16& l) {
    h = __float2bfloat16(x);
    l = __float2bfloat16(x - __bfloat162float(h));
}

__device__ __forceinline__ uint32_t cvta_s(const void* p) {
    return (uint32_t)__cvta_generic_to_shared(p);
}

__device__ __forceinline__ void ldsm_x4(uint32_t* r, uint32_t addr) {
    asm volatile("ldmatrix.sync.aligned.m8n8.x4.shared.b16 {%0,%1,%2,%3},[%4];\n"
                 : "=r"(r[0]), "=r"(r[1]), "=r"(r[2]), "=r"(r[3]) : "r"(addr));
}
__device__ __forceinline__ void ldsm_x4_t(uint32_t* r, uint32_t addr) {
    asm volatile("ldmatrix.sync.aligned.m8n8.x4.trans.shared.b16 {%0,%1,%2,%3},[%4];\n"
                 : "=r"(r[0]), "=r"(r[1]), "=r"(r[2]), "=r"(r[3]) : "r"(addr));
}
__device__ __forceinline__ void mma_bf16(float* c, const uint32_t* a, const uint32_t* b) {
    asm volatile(
        "mma.sync.aligned.m16n8k16.row.col.f32.bf16.bf16.f32 "
        "{%0,%1,%2,%3},{%4,%5,%6,%7},{%8,%9},{%0,%1,%2,%3};\n"
        : "+f"(c[0]), "+f"(c[1]), "+f"(c[2]), "+f"(c[3])
        : "r"(a[0]), "r"(a[1]), "r"(a[2]), "r"(a[3]), "r"(b[0]), "r"(b[1]));
}

__global__ __launch_bounds__(512, 1) void attn_bf16_kernel()
{
    extern __shared__ __nv_bfloat16 smb[];
    __nv_bfloat16* Qh = smb;                 // 64 x QLDb
    __nv_bfloat16* Ql = Qh + 64 * QLDb;
    __nv_bfloat16* Kh = Ql + 64 * QLDb;      // 64 x KLDb
    __nv_bfloat16* Kl = Kh + 64 * KLDb;
    __nv_bfloat16* Ph = Kl + 64 * KLDb;      // 64 x PLDb
    __nv_bfloat16* Pl = Ph + 64 * PLDb;
    __nv_bfloat16* Vh = Pl + 64 * PLDb;      // 256 x VLDb
    __nv_bfloat16* Vl = Vh + 256 * VLDb;

    const int b    = blockIdx.y;
    const int j0g  = blockIdx.x * 128;
    const int tid  = threadIdx.x;
    const int warp = tid >> 5;
    const int lane = tid & 31;

    const float* Qb = g_Q + (size_t)b * CKD * NN;
    const float* Kb = g_K + (size_t)b * CKD * NN;
    const float* Vb = g_V + (size_t)b * CDIM * NN;

    const uint32_t qh_b = cvta_s(Qh), ql_b = cvta_s(Ql);
    const uint32_t kh_b = cvta_s(Kh), kl_b = cvta_s(Kl);
    const uint32_t ph_b = cvta_s(Ph), pl_b = cvta_s(Pl);
    const uint32_t vh_b = cvta_s(Vh), vl_b = cvta_s(Vl);

    // --- load + split K tile once (64 d x 128 j) ---
#pragma unroll
    for (int r = 0; r < 4; ++r) {
        int idx4 = tid + r * 512;
        int d = idx4 >> 5, j = (idx4 & 31) * 4;
        float4 v = *(const float4*)&Kb[(size_t)d * NN + j0g + j];
        __nv_bfloat16 h0, l0, h1, l1, h2, l2, h3, l3;
        split2(v.x, h0, l0); split2(v.y, h1, l1);
        split2(v.z, h2, l2); split2(v.w, h3, l3);
        __nv_bfloat162 th, tl;
        th.x = h0; th.y = h1; tl.x = l0; tl.y = l1;
        *(__nv_bfloat162*)&Kh[d * KLDb + j]     = th;
        *(__nv_bfloat162*)&Kl[d * KLDb + j]     = tl;
        th.x = h2; th.y = h3; tl.x = l2; tl.y = l3;
        *(__nv_bfloat162*)&Kh[d * KLDb + j + 2] = th;
        *(__nv_bfloat162*)&Kl[d * KLDb + j + 2] = tl;
    }

    // ldmatrix lane address components
    const int l7 = lane & 7, rr = lane >> 3;
    const int a_dofs = ((rr & 2) << 2) + l7;      // + k0  (A trans: Q)
    const int a_iofs = ((rr & 1) << 3);           // + i0
    const int b_kofs = ((rr & 1) << 3) + l7;      // + k0  (B trans: K/P)
    const int b_jofs = ((rr & 2) << 2);           // + j0
    const int v_row  = (lane & 15);               // + c0  (A non-trans: V)
    const int v_col  = ((lane >> 4) << 3);        // + k0

    // warp mappings
    const int s_i0   = (warp >> 2) * 16;          // S: 4 i-blocks
    const int s_jb   = (warp & 3) * 32;           // S: 4 j-groups of 32
    const int o_c0   = warp * 16;                 // O: 16 c-blocks

    float oacc[16][4];
#pragma unroll
    for (int t = 0; t < 16; ++t)
#pragma unroll
        for (int e = 0; e < 4; ++e) oacc[t][e] = 0.f;

    for (int it = 0; it < 64; ++it) {
        const int i0g = it * 64;
        __syncthreads();  // previous O-phase done with Qs/Vs/Ps

        // load + split Q tile (64 d x 64 i)
#pragma unroll
        for (int r = 0; r < 2; ++r) {
            int idx4 = tid + r * 512;
            int d = idx4 >> 4, i = (idx4 & 15) * 4;
            float4 v = *(const float4*)&Qb[(size_t)d * NN + i0g + i];
            __nv_bfloat16 h0, l0, h1, l1, h2, l2, h3, l3;
            split2(v.x, h0, l0); split2(v.y, h1, l1);
            split2(v.z, h2, l2); split2(v.w, h3, l3);
            __nv_bfloat162 th, tl;
            th.x = h0; th.y = h1; tl.x = l0; tl.y = l1;
            *(__nv_bfloat162*)&Qh[d * QLDb + i]     = th;
            *(__nv_bfloat162*)&Ql[d * QLDb + i]     = tl;
            th.x = h2; th.y = h3; tl.x = l2; tl.y = l3;
            *(__nv_bfloat162*)&Qh[d * QLDb + i + 2] = th;
            *(__nv_bfloat162*)&Ql[d * QLDb + i + 2] = tl;
        }
        // load + split V tile (256 c x 64 i)
#pragma unroll
        for (int r = 0; r < 8; ++r) {
            int idx4 = tid + r * 512;
            int c = idx4 >> 4, i = (idx4 & 15) * 4;
            float4 v = *(const float4*)&Vb[(size_t)c * NN + i0g + i];
            __nv_bfloat16 h0, l0, h1, l1, h2, l2, h3, l3;
            split2(v.x, h0, l0); split2(v.y, h1, l1);
            split2(v.z, h2, l2); split2(v.w, h3, l3);
            __nv_bfloat162 th, tl;
            th.x = h0; th.y = h1; tl.x = l0; tl.y = l1;
            *(__nv_bfloat162*)&Vh[c * VLDb + i]     = th;
            *(__nv_bfloat162*)&Vl[c * VLDb + i]     = tl;
            th.x = h2; th.y = h3; tl.x = l2; tl.y = l3;
            *(__nv_bfloat162*)&Vh[c * VLDb + i + 2] = th;
            *(__nv_bfloat162*)&Vl[c * VLDb + i + 2] = tl;
        }
        __syncthreads();

        // ---- S = Q^T K  (warp: 16 i x 32 j) ----
        {
            float sacc[4][4];
#pragma unroll
            for (int t = 0; t < 4; ++t)
#pragma unroll
                for (int e = 0; e < 4; ++e) sacc[t][e] = 0.f;

#pragma unroll
            for (int k0 = 0; k0 < 64; k0 += 16) {
                uint32_t ah[4], al[4];
                uint32_t aoff = (uint32_t)((k0 + a_dofs) * QLDb + s_i0 + a_iofs) * 2;
                ldsm_x4_t(ah, qh_b + aoff);
                ldsm_x4_t(al, ql_b + aoff);
#pragma unroll
                for (int jj = 0; jj < 2; ++jj) {
                    int j0 = s_jb + jj * 16;
                    uint32_t bh[4], bl[4];
                    uint32_t boff = (uint32_t)((k0 + b_kofs) * KLDb + j0 + b_jofs) * 2;
                    ldsm_x4_t(bh, kh_b + boff);
                    ldsm_x4_t(bl, kl_b + boff);
                    mma_bf16(sacc[jj * 2 + 0], ah, bh + 0);
                    mma_bf16(sacc[jj * 2 + 0], ah, bl + 0);
                    mma_bf16(sacc[jj * 2 + 0], al, bh + 0);
                    mma_bf16(sacc[jj * 2 + 1], ah, bh + 2);
                    mma_bf16(sacc[jj * 2 + 1], ah, bl + 2);
                    mma_bf16(sacc[jj * 2 + 1], al, bh + 2);
                }
            }

            // P = elu(S)/N, split to bf16 hi/lo in smem
            int prow = s_i0 + (lane >> 2);
            int pcol = (lane & 3) * 2;
#pragma unroll
            for (int t = 0; t < 4; ++t) {
                int jc = s_jb + t * 8 + pcol;
                float p0 = elu_scaled(sacc[t][0]);
                float p1 = elu_scaled(sacc[t][1]);
                float p2 = elu_scaled(sacc[t][2]);
                float p3 = elu_scaled(sacc[t][3]);
                __nv_bfloat16 h0, l0, h1, l1;
                split2(p0, h0, l0); split2(p1, h1, l1);
                __nv_bfloat162 th, tl;
                th.x = h0; th.y = h1; tl.x = l0; tl.y = l1;
                *(__nv_bfloat162*)&Ph[prow * PLDb + jc] = th;
                *(__nv_bfloat162*)&Pl[prow * PLDb + jc] = tl;
                split2(p2, h0, l0); split2(p3, h1, l1);
                th.x = h0; th.y = h1; tl.x = l0; tl.y = l1;
                *(__nv_bfloat162*)&Ph[(prow + 8) * PLDb + jc] = th;
                *(__nv_bfloat162*)&Pl[(prow + 8) * PLDb + jc] = tl;
            }
        }
        __syncthreads();

        // ---- O[c,j] += V P  (warp: 16 c x 128 j) ----
#pragma unroll
        for (int k0 = 0; k0 < 64; k0 += 16) {
            uint32_t vh[4], vl[4];
            uint32_t voff = (uint32_t)((o_c0 + v_row) * VLDb + k0 + v_col) * 2;
            ldsm_x4(vh, vh_b + voff);
            ldsm_x4(vl, vl_b + voff);
#pragma unroll
            for (int jj = 0; jj < 8; ++jj) {
                int j0 = jj * 16;
                uint32_t ph[4], pl[4];
                uint32_t boff = (uint32_t)((k0 + b_kofs) * PLDb + j0 + b_jofs) * 2;
                ldsm_x4_t(ph, ph_b + boff);
                ldsm_x4_t(pl, pl_b + boff);
                mma_bf16(oacc[jj * 2 + 0], vh, ph + 0);
                mma_bf16(oacc[jj * 2 + 0], vh, pl + 0);
                mma_bf16(oacc[jj * 2 + 0], vl, ph + 0);
                mma_bf16(oacc[jj * 2 + 1], vh, ph + 2);
                mma_bf16(oacc[jj * 2 + 1], vh, pl + 2);
                mma_bf16(oacc[jj * 2 + 1], vl, ph + 2);
            }
        }
    }

    // ---- store O accumulators to global scratch ----
    float* Ob = g_O + (size_t)b * CDIM * NN;
    int orow = o_c0 + (lane >> 2);
    int ocol = (lane & 3) * 2;
#pragma unroll
    for (int t = 0; t < 16; ++t) {
        int j = j0g + t * 8 + ocol;
        float2 r0 = {oacc[t][0], oacc[t][1]};
        float2 r1 = {oacc[t][2], oacc[t][3]};
        *(float2*)&Ob[(size_t)orow * NN + j]       = r0;
        *(float2*)&Ob[(size_t)(orow + 8) * NN + j] = r1;
    }
}

// ---------------------------------------------------------------------------
extern "C" void kernel_launch(void* const* d_in, const int* in_sizes, int n_in,
                              void* d_out, int out_size)
{
    const float* x  = (const float*)d_in[0];
    const float* wq = (const float*)d_in[1];
    const float* bq = (const float*)d_in[2];
    const float* wk = (const float*)d_in[3];
    const float* bk = (const float*)d_in[4];
    const float* wv = (const float*)d_in[5];
    const float* bv = (const float*)d_in[6];
    const float* wg = (const float*)d_in[7];
    const float* bg = (const float*)d_in[8];
    float* out = (float*)d_out;

    float *Qp, *Kp, *Vp, *Op;
    cudaGetSymbolAddress((void**)&Qp, g_Q);
    cudaGetSymbolAddress((void**)&Kp, g_K);
    cudaGetSymbolAddress((void**)&Vp, g_V);
    cudaGetSymbolAddress((void**)&Op, g_O);

    const int smem_attn =
        (2 * 64 * QLDb + 2 * 64 * KLDb + 2 * 64 * PLDb + 2 * 256 * VLDb) * 2; // 161792
    cudaFuncSetAttribute(attn_bf16_kernel, cudaFuncAttributeMaxDynamicSharedMemorySize,
                         smem_attn);

    // QKV projections
    proj_kernel<<<dim3(NN / 128, CKD  / 64, NB), 256>>>(wq, bq, x, Qp, CKD);
    proj_kernel<<<dim3(NN / 128, CKD  / 64, NB), 256>>>(wk, bk, x, Kp, CKD);
    proj_kernel<<<dim3(NN / 128, CDIM / 64, NB), 256>>>(wv, bv, x, Vp, CDIM);

    // Fused attention on tensor cores (energy never materialized)
    attn_bf16_kernel<<<dim3(NN / 128, NB), 512, smem_attn>>>();

    // Final 1x1 conv (wg)
    proj_kernel<<<dim3(NN / 128, CDIM / 64, NB), 256>>>(wg, bg, Op, out, CDIM);
}

// round 6
// speedup vs baseline: 2.5422x; 1.2191x over previous
#include <cuda_runtime.h>
#include <cuda_bf16.h>
#include <math.h>
#include <stdint.h>

#define NB   8
#define CDIM 256
#define CKD  64
#define NN   4096

// ---------------------------------------------------------------------------
// Scratch (allocation-free rule: __device__ globals). All split bf16 hi/lo.
// ---------------------------------------------------------------------------
__device__ __nv_bfloat16 g_xh[NB * CDIM * NN], g_xl[NB * CDIM * NN];
__device__ __nv_bfloat16 g_Qh[NB * CKD  * NN], g_Ql[NB * CKD  * NN];
__device__ __nv_bfloat16 g_Kh[NB * CKD  * NN], g_Kl[NB * CKD  * NN];
__device__ __nv_bfloat16 g_Vh[NB * CDIM * NN], g_Vl[NB * CDIM * NN];
__device__ __nv_bfloat16 g_Oh[NB * CDIM * NN], g_Ol[NB * CDIM * NN];

// ---------------------------------------------------------------------------
// Helpers (validated in R4)
// ---------------------------------------------------------------------------
__device__ __forceinline__ float elu_scaled(float x) {
    const float invN = 1.0f / 4096.0f;
    return (x > 0.f ? x : (expf(x) - 1.f)) * invN;
}
__device__ __forceinline__ void split2(float x, __nv_bfloat16& h, __nv_bfloat16& l) {
    h = __float2bfloat16(x);
    l = __float2bfloat16(x - __bfloat162float(h));
}
__device__ __forceinline__ uint32_t cvta_s(const void* p) {
    return (uint32_t)__cvta_generic_to_shared(p);
}
__device__ __forceinline__ void ldsm_x4(uint32_t* r, uint32_t addr) {
    asm volatile("ldmatrix.sync.aligned.m8n8.x4.shared.b16 {%0,%1,%2,%3},[%4];\n"
                 : "=r"(r[0]), "=r"(r[1]), "=r"(r[2]), "=r"(r[3]) : "r"(addr));
}
__device__ __forceinline__ void ldsm_x4_t(uint32_t* r, uint32_t addr) {
    asm volatile("ldmatrix.sync.aligned.m8n8.x4.trans.shared.b16 {%0,%1,%2,%3},[%4];\n"
                 : "=r"(r[0]), "=r"(r[1]), "=r"(r[2]), "=r"(r[3]) : "r"(addr));
}
__device__ __forceinline__ void mma_bf16(float* c, const uint32_t* a, const uint32_t* b) {
    asm volatile(
        "mma.sync.aligned.m16n8k16.row.col.f32.bf16.bf16.f32 "
        "{%0,%1,%2,%3},{%4,%5,%6,%7},{%8,%9},{%0,%1,%2,%3};\n"
        : "+f"(c[0]), "+f"(c[1]), "+f"(c[2]), "+f"(c[3])
        : "r"(a[0]), "r"(a[1]), "r"(a[2]), "r"(a[3]), "r"(b[0]), "r"(b[1]));
}

// ---------------------------------------------------------------------------
// Split x (fp32 -> bf16 hi/lo), vectorized. n4 = elements/4.
// ---------------------------------------------------------------------------
__global__ __launch_bounds__(256) void split_kernel(
    const float4* __restrict__ in, __nv_bfloat162* __restrict__ oh,
    __nv_bfloat162* __restrict__ ol, int n4)
{
    int i = blockIdx.x * blockDim.x + threadIdx.x;
    if (i >= n4) return;
    float4 v = in[i];
    __nv_bfloat16 h0, l0, h1, l1, h2, l2, h3, l3;
    split2(v.x, h0, l0); split2(v.y, h1, l1);
    split2(v.z, h2, l2); split2(v.w, h3, l3);
    __nv_bfloat162 a, b;
    a.x = h0; a.y = h1; b.x = h2; b.y = h3;
    oh[i * 2] = a; oh[i * 2 + 1] = b;
    a.x = l0; a.y = l1; b.x = l2; b.y = l3;
    ol[i * 2] = a; ol[i * 2 + 1] = b;
}

// ---------------------------------------------------------------------------
// Tensor-core projection: Y[b,o,n] = sum_c W[o,c] X[b,c,n] + bias[o]
// X given as pre-split bf16 hi/lo. Output: split bf16 (Yh/Yl) or fp32 (Yf).
// CTA: 64o x 128n, K=256 in 4 chunks of 64. 256 threads (8 warps, 16o x 64n).
// smem: Wh/Wl [64][72] + Xsh/Xsl [64][136] = 53.25 KB (dynamic)
// ---------------------------------------------------------------------------
#define WLD 72
#define XLD 136

__global__ __launch_bounds__(256) void proj_mma_kernel(
    const float* __restrict__ W, const float* __restrict__ bias,
    const __nv_bfloat16* __restrict__ Xh, const __nv_bfloat16* __restrict__ Xl,
    __nv_bfloat16* __restrict__ Yh, __nv_bfloat16* __restrict__ Yl,
    float* __restrict__ Yf, int R)
{
    extern __shared__ __nv_bfloat16 sp[];
    __nv_bfloat16* Wh  = sp;                    // [64][WLD]
    __nv_bfloat16* Wl  = Wh  + 64 * WLD;
    __nv_bfloat16* Xsh = Wl  + 64 * WLD;        // [64][XLD]
    __nv_bfloat16* Xsl = Xsh + 64 * XLD;

    const int b  = blockIdx.z;
    const int o0 = blockIdx.y * 64;
    const int n0 = blockIdx.x * 128;
    const int tid  = threadIdx.x;
    const int warp = tid >> 5;
    const int lane = tid & 31;

    const __nv_bfloat16* Xbh = Xh + (size_t)b * CDIM * NN;
    const __nv_bfloat16* Xbl = Xl + (size_t)b * CDIM * NN;

    const uint32_t wh_b = cvta_s(Wh), wl_b = cvta_s(Wl);
    const uint32_t xh_b = cvta_s(Xsh), xl_b = cvta_s(Xsl);

    const int l7 = lane & 7, rr = lane >> 3;
    const int a_kofs = ((rr & 2) << 2) + l7;
    const int a_mofs = ((rr & 1) << 3);
    const int b_kofs = ((rr & 1) << 3) + l7;
    const int b_nofs = ((rr & 2) << 2);

    const int wo = warp >> 1;     // 4 o-groups of 16
    const int wn = warp & 1;      // 2 n-groups of 64

    float acc[8][4];
#pragma unroll
    for (int t = 0; t < 8; ++t)
#pragma unroll
        for (int e = 0; e < 4; ++e) acc[t][e] = 0.f;

    for (int kc = 0; kc < 4; ++kc) {
        // load + split W chunk (64o x 64c) -> Wh/Wl[cc][o]
#pragma unroll
        for (int r = 0; r < 16; ++r) {
            int idx = tid + r * 256;
            int o = idx >> 6, cc = idx & 63;
            float w = W[(size_t)(o0 + o) * CDIM + kc * 64 + cc];
            __nv_bfloat16 h, l;
            split2(w, h, l);
            Wh[cc * WLD + o] = h;
            Wl[cc * WLD + o] = l;
        }
        // copy X chunk (64c x 128n), bf16 direct
#pragma unroll
        for (int r = 0; r < 4; ++r) {
            int idx = tid + r * 256;
            int row = idx >> 4, c4 = idx & 15;
            *(uint4*)&Xsh[row * XLD + c4 * 8] =
                *(const uint4*)(Xbh + (size_t)(kc * 64 + row) * NN + n0 + c4 * 8);
            *(uint4*)&Xsl[row * XLD + c4 * 8] =
                *(const uint4*)(Xbl + (size_t)(kc * 64 + row) * NN + n0 + c4 * 8);
        }
        __syncthreads();

#pragma unroll
        for (int k0 = 0; k0 < 64; k0 += 16) {
            uint32_t ah[4], al[4];
            uint32_t aoff = (uint32_t)((k0 + a_kofs) * WLD + wo * 16 + a_mofs) * 2;
            ldsm_x4_t(ah, wh_b + aoff);
            ldsm_x4_t(al, wl_b + aoff);
#pragma unroll
            for (int jj = 0; jj < 4; ++jj) {
                uint32_t bh[4], bl[4];
                uint32_t boff =
                    (uint32_t)((k0 + b_kofs) * XLD + wn * 64 + jj * 16 + b_nofs) * 2;
                ldsm_x4_t(bh, xh_b + boff);
                ldsm_x4_t(bl, xl_b + boff);
                mma_bf16(acc[jj * 2 + 0], ah, bh + 0);
                mma_bf16(acc[jj * 2 + 0], ah, bl + 0);
                mma_bf16(acc[jj * 2 + 0], al, bh + 0);
                mma_bf16(acc[jj * 2 + 1], ah, bh + 2);
                mma_bf16(acc[jj * 2 + 1], ah, bl + 2);
                mma_bf16(acc[jj * 2 + 1], al, bh + 2);
            }
        }
        __syncthreads();
    }

    // epilogue: + bias, write split bf16 or fp32
    const int orow = wo * 16 + (lane >> 2);
    const float b0 = bias[o0 + orow];
    const float b1 = bias[o0 + orow + 8];
#pragma unroll
    for (int t = 0; t < 8; ++t) {
        int col = n0 + wn * 64 + t * 8 + (lane & 3) * 2;
        float v00 = acc[t][0] + b0, v01 = acc[t][1] + b0;
        float v10 = acc[t][2] + b1, v11 = acc[t][3] + b1;
        size_t i0 = ((size_t)b * R + o0 + orow) * NN + col;
        size_t i1 = ((size_t)b * R + o0 + orow + 8) * NN + col;
        if (Yf) {
            *(float2*)&Yf[i0] = make_float2(v00, v01);
            *(float2*)&Yf[i1] = make_float2(v10, v11);
        } else {
            __nv_bfloat16 h0, l0, h1, l1;
            __nv_bfloat162 th, tl;
            split2(v00, h0, l0); split2(v01, h1, l1);
            th.x = h0; th.y = h1; tl.x = l0; tl.y = l1;
            *(__nv_bfloat162*)&Yh[i0] = th;
            *(__nv_bfloat162*)&Yl[i0] = tl;
            split2(v10, h0, l0); split2(v11, h1, l1);
            th.x = h0; th.y = h1; tl.x = l0; tl.y = l1;
            *(__nv_bfloat162*)&Yh[i1] = th;
            *(__nv_bfloat162*)&Yl[i1] = tl;
        }
    }
}

// ---------------------------------------------------------------------------
// Fused attention, pre-split bf16 inputs. Per CTA: (b, 128 j). i tiled by 64.
//   S = Q^T K -> P = elu(S)/N (split) -> O += V P. O written split bf16.
// smem 161.8 KB (dynamic). S warps: 16i x 32j. O warps: 32c x 64j.
// ---------------------------------------------------------------------------
#define QLDb 72
#define KLDb 136
#define PLDb 136
#define VLDb 72

__global__ __launch_bounds__(512) void attn_bf16_kernel()
{
    extern __shared__ __nv_bfloat16 smb[];
    __nv_bfloat16* Qh = smb;                 // 64 x QLDb
    __nv_bfloat16* Ql = Qh + 64 * QLDb;
    __nv_bfloat16* Kh = Ql + 64 * QLDb;      // 64 x KLDb
    __nv_bfloat16* Kl = Kh + 64 * KLDb;
    __nv_bfloat16* Ph = Kl + 64 * KLDb;      // 64 x PLDb
    __nv_bfloat16* Pl = Ph + 64 * PLDb;
    __nv_bfloat16* Vh = Pl + 64 * PLDb;      // 256 x VLDb
    __nv_bfloat16* Vl = Vh + 256 * VLDb;

    const int b    = blockIdx.y;
    const int j0g  = blockIdx.x * 128;
    const int tid  = threadIdx.x;
    const int warp = tid >> 5;
    const int lane = tid & 31;

    const __nv_bfloat16* Qbh = g_Qh + (size_t)b * CKD * NN;
    const __nv_bfloat16* Qbl = g_Ql + (size_t)b * CKD * NN;
    const __nv_bfloat16* Kbh = g_Kh + (size_t)b * CKD * NN;
    const __nv_bfloat16* Kbl = g_Kl + (size_t)b * CKD * NN;
    const __nv_bfloat16* Vbh = g_Vh + (size_t)b * CDIM * NN;
    const __nv_bfloat16* Vbl = g_Vl + (size_t)b * CDIM * NN;

    const uint32_t qh_b = cvta_s(Qh), ql_b = cvta_s(Ql);
    const uint32_t kh_b = cvta_s(Kh), kl_b = cvta_s(Kl);
    const uint32_t ph_b = cvta_s(Ph), pl_b = cvta_s(Pl);
    const uint32_t vh_b = cvta_s(Vh), vl_b = cvta_s(Vl);

    // --- load K tile once (64 d x 128 j), bf16 direct copies ---
#pragma unroll
    for (int r = 0; r < 2; ++r) {
        int idx = tid + r * 512;
        int row = idx >> 4, c4 = idx & 15;
        *(uint4*)&Kh[row * KLDb + c4 * 8] =
            *(const uint4*)(Kbh + (size_t)row * NN + j0g + c4 * 8);
    }
#pragma unroll
    for (int r = 0; r < 2; ++r) {
        int idx = tid + r * 512;
        int row = idx >> 4, c4 = idx & 15;
        *(uint4*)&Kl[row * KLDb + c4 * 8] =
            *(const uint4*)(Kbl + (size_t)row * NN + j0g + c4 * 8);
    }

    // ldmatrix lane components (validated R4)
    const int l7 = lane & 7, rr = lane >> 3;
    const int a_dofs = ((rr & 2) << 2) + l7;      // A-trans: +k
    const int a_iofs = ((rr & 1) << 3);           // A-trans: +m
    const int b_kofs = ((rr & 1) << 3) + l7;      // B-trans: +k
    const int b_jofs = ((rr & 2) << 2);           // B-trans: +n
    const int v_row  = (lane & 15);               // A non-trans: +m
    const int v_col  = ((lane >> 4) << 3);        // A non-trans: +k

    // warp mappings
    const int s_i0 = (warp >> 2) * 16;            // S: 4 i-blocks
    const int s_jb = (warp & 3) * 32;             // S: 4 j-groups of 32
    const int o_c0 = (warp >> 1) * 32;            // O: 8 c-groups of 32
    const int o_j0 = (warp & 1) * 64;             // O: 2 j-groups of 64

    float oacc[16][4];   // [cb*8 + jj*2 + h][e], cb in 0..1, jj in 0..3, h in 0..1
#pragma unroll
    for (int t = 0; t < 16; ++t)
#pragma unroll
        for (int e = 0; e < 4; ++e) oacc[t][e] = 0.f;

    for (int it = 0; it < 64; ++it) {
        const int i0g = it * 64;
        __syncthreads();  // previous O-phase done with Qs/Vs/Ps

        // Q tile (64 d x 64 i): 512 uint4 per array
        {
            int row = tid >> 3, c4 = tid & 7;
            *(uint4*)&Qh[row * QLDb + c4 * 8] =
                *(const uint4*)(Qbh + (size_t)row * NN + i0g + c4 * 8);
            *(uint4*)&Ql[row * QLDb + c4 * 8] =
                *(const uint4*)(Qbl + (size_t)row * NN + i0g + c4 * 8);
        }
        // V tile (256 c x 64 i): 2048 uint4 per array
#pragma unroll
        for (int r = 0; r < 4; ++r) {
            int idx = tid + r * 512;
            int row = idx >> 3, c4 = idx & 7;
            *(uint4*)&Vh[row * VLDb + c4 * 8] =
                *(const uint4*)(Vbh + (size_t)row * NN + i0g + c4 * 8);
            *(uint4*)&Vl[row * VLDb + c4 * 8] =
                *(const uint4*)(Vbl + (size_t)row * NN + i0g + c4 * 8);
        }
        __syncthreads();

        // ---- S = Q^T K (warp: 16i x 32j) ----
        {
            float sacc[4][4];
#pragma unroll
            for (int t = 0; t < 4; ++t)
#pragma unroll
                for (int e = 0; e < 4; ++e) sacc[t][e] = 0.f;

#pragma unroll
            for (int k0 = 0; k0 < 64; k0 += 16) {
                uint32_t ah[4], al[4];
                uint32_t aoff = (uint32_t)((k0 + a_dofs) * QLDb + s_i0 + a_iofs) * 2;
                ldsm_x4_t(ah, qh_b + aoff);
                ldsm_x4_t(al, ql_b + aoff);
#pragma unroll
                for (int jj = 0; jj < 2; ++jj) {
                    int j0 = s_jb + jj * 16;
                    uint32_t bh[4], bl[4];
                    uint32_t boff = (uint32_t)((k0 + b_kofs) * KLDb + j0 + b_jofs) * 2;
                    ldsm_x4_t(bh, kh_b + boff);
                    ldsm_x4_t(bl, kl_b + boff);
                    mma_bf16(sacc[jj * 2 + 0], ah, bh + 0);
                    mma_bf16(sacc[jj * 2 + 0], ah, bl + 0);
                    mma_bf16(sacc[jj * 2 + 0], al, bh + 0);
                    mma_bf16(sacc[jj * 2 + 1], ah, bh + 2);
                    mma_bf16(sacc[jj * 2 + 1], ah, bl + 2);
                    mma_bf16(sacc[jj * 2 + 1], al, bh + 2);
                }
            }

            // P = elu(S)/N, split hi/lo to smem
            int prow = s_i0 + (lane >> 2);
            int pcol = (lane & 3) * 2;
#pragma unroll
            for (int t = 0; t < 4; ++t) {
                int jc = s_jb + t * 8 + pcol;
                float p0 = elu_scaled(sacc[t][0]);
                float p1 = elu_scaled(sacc[t][1]);
                float p2 = elu_scaled(sacc[t][2]);
                float p3 = elu_scaled(sacc[t][3]);
                __nv_bfloat16 h0, l0, h1, l1;
                __nv_bfloat162 th, tl;
                split2(p0, h0, l0); split2(p1, h1, l1);
                th.x = h0; th.y = h1; tl.x = l0; tl.y = l1;
                *(__nv_bfloat162*)&Ph[prow * PLDb + jc] = th;
                *(__nv_bfloat162*)&Pl[prow * PLDb + jc] = tl;
                split2(p2, h0, l0); split2(p3, h1, l1);
                th.x = h0; th.y = h1; tl.x = l0; tl.y = l1;
                *(__nv_bfloat162*)&Ph[(prow + 8) * PLDb + jc] = th;
                *(__nv_bfloat162*)&Pl[(prow + 8) * PLDb + jc] = tl;
            }
        }
        __syncthreads();

        // ---- O[c,j] += V P (warp: 32c x 64j) ----
#pragma unroll
        for (int k0 = 0; k0 < 64; k0 += 16) {
            uint32_t vh0[4], vl0[4], vh1[4], vl1[4];
            {
                uint32_t voff0 = (uint32_t)((o_c0 + v_row) * VLDb + k0 + v_col) * 2;
                uint32_t voff1 = (uint32_t)((o_c0 + 16 + v_row) * VLDb + k0 + v_col) * 2;
                ldsm_x4(vh0, vh_b + voff0);
                ldsm_x4(vl0, vl_b + voff0);
                ldsm_x4(vh1, vh_b + voff1);
                ldsm_x4(vl1, vl_b + voff1);
            }
#pragma unroll
            for (int jj = 0; jj < 4; ++jj) {
                uint32_t ph[4], pl[4];
                uint32_t boff =
                    (uint32_t)((k0 + b_kofs) * PLDb + o_j0 + jj * 16 + b_jofs) * 2;
                ldsm_x4_t(ph, ph_b + boff);
                ldsm_x4_t(pl, pl_b + boff);
                mma_bf16(oacc[jj * 2 + 0], vh0, ph + 0);
                mma_bf16(oacc[jj * 2 + 0], vh0, pl + 0);
                mma_bf16(oacc[jj * 2 + 0], vl0, ph + 0);
                mma_bf16(oacc[jj * 2 + 1], vh0, ph + 2);
                mma_bf16(oacc[jj * 2 + 1], vh0, pl + 2);
                mma_bf16(oacc[jj * 2 + 1], vl0, ph + 2);
                mma_bf16(oacc[8 + jj * 2 + 0], vh1, ph + 0);
                mma_bf16(oacc[8 + jj * 2 + 0], vh1, pl + 0);
                mma_bf16(oacc[8 + jj * 2 + 0], vl1, ph + 0);
                mma_bf16(oacc[8 + jj * 2 + 1], vh1, ph + 2);
                mma_bf16(oacc[8 + jj * 2 + 1], vh1, pl + 2);
                mma_bf16(oacc[8 + jj * 2 + 1], vl1, ph + 2);
            }
        }
    }

    // ---- store O accumulators, split bf16, to scratch ----
#pragma unroll
    for (int cb = 0; cb < 2; ++cb) {
        int orow = o_c0 + cb * 16 + (lane >> 2);
#pragma unroll
        for (int jj = 0; jj < 4; ++jj) {
#pragma unroll
            for (int h = 0; h < 2; ++h) {
                float* a = oacc[cb * 8 + jj * 2 + h];
                int col = j0g + o_j0 + jj * 16 + h * 8 + (lane & 3) * 2;
                size_t i0 = ((size_t)b * CDIM + orow) * NN + col;
                size_t i1 = ((size_t)b * CDIM + orow + 8) * NN + col;
                __nv_bfloat16 h0, l0, h1, l1;
                __nv_bfloat162 th, tl;
                split2(a[0], h0, l0); split2(a[1], h1, l1);
                th.x = h0; th.y = h1; tl.x = l0; tl.y = l1;
                *(__nv_bfloat162*)&g_Oh[i0] = th;
                *(__nv_bfloat162*)&g_Ol[i0] = tl;
                split2(a[2], h0, l0); split2(a[3], h1, l1);
                th.x = h0; th.y = h1; tl.x = l0; tl.y = l1;
                *(__nv_bfloat162*)&g_Oh[i1] = th;
                *(__nv_bfloat162*)&g_Ol[i1] = tl;
            }
        }
    }
}

// ---------------------------------------------------------------------------
extern "C" void kernel_launch(void* const* d_in, const int* in_sizes, int n_in,
                              void* d_out, int out_size)
{
    const float* x  = (const float*)d_in[0];
    const float* wq = (const float*)d_in[1];
    const float* bq = (const float*)d_in[2];
    const float* wk = (const float*)d_in[3];
    const float* bk = (const float*)d_in[4];
    const float* wv = (const float*)d_in[5];
    const float* bv = (const float*)d_in[6];
    const float* wg = (const float*)d_in[7];
    const float* bg = (const float*)d_in[8];
    float* out = (float*)d_out;

    __nv_bfloat16 *xh, *xl, *Qh, *Ql, *Kh, *Kl, *Vh, *Vl, *Oh, *Ol;
    cudaGetSymbolAddress((void**)&xh, g_xh);
    cudaGetSymbolAddress((void**)&xl, g_xl);
    cudaGetSymbolAddress((void**)&Qh, g_Qh);
    cudaGetSymbolAddress((void**)&Ql, g_Ql);
    cudaGetSymbolAddress((void**)&Kh, g_Kh);
    cudaGetSymbolAddress((void**)&Kl, g_Kl);
    cudaGetSymbolAddress((void**)&Vh, g_Vh);
    cudaGetSymbolAddress((void**)&Vl, g_Vl);
    cudaGetSymbolAddress((void**)&Oh, g_Oh);
    cudaGetSymbolAddress((void**)&Ol, g_Ol);

    const int smem_attn =
        (2 * 64 * QLDb + 2 * 64 * KLDb + 2 * 64 * PLDb + 2 * 256 * VLDb) * 2;
    cudaFuncSetAttribute(attn_bf16_kernel, cudaFuncAttributeMaxDynamicSharedMemorySize,
                         smem_attn);
    const int smem_proj = (2 * 64 * WLD + 2 * 64 * XLD) * 2;
    cudaFuncSetAttribute(proj_mma_kernel, cudaFuncAttributeMaxDynamicSharedMemorySize,
                         smem_proj);

    // 1. split x -> bf16 hi/lo
    const int n4 = NB * CDIM * NN / 4;
    split_kernel<<<(n4 + 255) / 256, 256>>>(
        (const float4*)x, (__nv_bfloat162*)xh, (__nv_bfloat162*)xl, n4);

    // 2. QKV projections on tensor cores (split bf16 out)
    proj_mma_kernel<<<dim3(NN / 128, CKD / 64, NB), 256, smem_proj>>>(
        wq, bq, xh, xl, Qh, Ql, nullptr, CKD);
    proj_mma_kernel<<<dim3(NN / 128, CKD / 64, NB), 256, smem_proj>>>(
        wk, bk, xh, xl, Kh, Kl, nullptr, CKD);
    proj_mma_kernel<<<dim3(NN / 128, CDIM / 64, NB), 256, smem_proj>>>(
        wv, bv, xh, xl, Vh, Vl, nullptr, CDIM);

    // 3. Fused attention (energy never materialized), split bf16 out
    attn_bf16_kernel<<<dim3(NN / 128, NB), 512, smem_attn>>>();

    // 4. Final 1x1 conv (wg) -> fp32 output
    proj_mma_kernel<<<dim3(NN / 128, CDIM / 64, NB), 256, smem_proj>>>(
        wg, bg, Oh, Ol, nullptr, nullptr, out, CDIM);
}

// round 7
// speedup vs baseline: 2.7698x; 1.0895x over previous
#include <cuda_runtime.h>
#include <cuda_bf16.h>
#include <math.h>
#include <stdint.h>

#define NB   8
#define CDIM 256
#define CKD  64
#define NN   4096

// ---------------------------------------------------------------------------
// Scratch (allocation-free rule: __device__ globals). All split bf16 hi/lo.
// ---------------------------------------------------------------------------
__device__ __nv_bfloat16 g_xh[NB * CDIM * NN], g_xl[NB * CDIM * NN];
__device__ __nv_bfloat16 g_Qh[NB * CKD  * NN], g_Ql[NB * CKD  * NN];
__device__ __nv_bfloat16 g_Kh[NB * CKD  * NN], g_Kl[NB * CKD  * NN];
__device__ __nv_bfloat16 g_Vh[NB * CDIM * NN], g_Vl[NB * CDIM * NN];
__device__ __nv_bfloat16 g_Oh[NB * CDIM * NN], g_Ol[NB * CDIM * NN];
// pre-split weights
__device__ __nv_bfloat16 g_Wqh[CKD * CDIM],  g_Wql[CKD * CDIM];
__device__ __nv_bfloat16 g_Wkh[CKD * CDIM],  g_Wkl[CKD * CDIM];
__device__ __nv_bfloat16 g_Wvh[CDIM * CDIM], g_Wvl[CDIM * CDIM];
__device__ __nv_bfloat16 g_Wgh[CDIM * CDIM], g_Wgl[CDIM * CDIM];

// ---------------------------------------------------------------------------
// Helpers (fragment maps validated in R4/R5)
// ---------------------------------------------------------------------------
__device__ __forceinline__ float elu_scaled(float x) {
    const float invN = 1.0f / 4096.0f;
    return (x > 0.f ? x : (expf(x) - 1.f)) * invN;
}
__device__ __forceinline__ void split2(float x, __nv_bfloat16& h, __nv_bfloat16& l) {
    h = __float2bfloat16(x);
    l = __float2bfloat16(x - __bfloat162float(h));
}
__device__ __forceinline__ uint32_t cvta_s(const void* p) {
    return (uint32_t)__cvta_generic_to_shared(p);
}
__device__ __forceinline__ void ldsm_x4(uint32_t* r, uint32_t addr) {
    asm volatile("ldmatrix.sync.aligned.m8n8.x4.shared.b16 {%0,%1,%2,%3},[%4];\n"
                 : "=r"(r[0]), "=r"(r[1]), "=r"(r[2]), "=r"(r[3]) : "r"(addr));
}
__device__ __forceinline__ void ldsm_x4_t(uint32_t* r, uint32_t addr) {
    asm volatile("ldmatrix.sync.aligned.m8n8.x4.trans.shared.b16 {%0,%1,%2,%3},[%4];\n"
                 : "=r"(r[0]), "=r"(r[1]), "=r"(r[2]), "=r"(r[3]) : "r"(addr));
}
__device__ __forceinline__ void mma_bf16(float* c, const uint32_t* a, const uint32_t* b) {
    asm volatile(
        "mma.sync.aligned.m16n8k16.row.col.f32.bf16.bf16.f32 "
        "{%0,%1,%2,%3},{%4,%5,%6,%7},{%8,%9},{%0,%1,%2,%3};\n"
        : "+f"(c[0]), "+f"(c[1]), "+f"(c[2]), "+f"(c[3])
        : "r"(a[0]), "r"(a[1]), "r"(a[2]), "r"(a[3]), "r"(b[0]), "r"(b[1]));
}
__device__ __forceinline__ void cp16(uint32_t saddr, const void* g) {
    asm volatile("cp.async.cg.shared.global [%0],[%1],16;\n" :: "r"(saddr), "l"(g));
}
__device__ __forceinline__ void cp_commit() {
    asm volatile("cp.async.commit_group;\n" ::: "memory");
}
template <int N> __device__ __forceinline__ void cp_wait() {
    asm volatile("cp.async.wait_group %0;\n" :: "n"(N) : "memory");
}

// ---------------------------------------------------------------------------
// Split fp32 -> bf16 hi/lo, vectorized. n4 = elements/4.
// ---------------------------------------------------------------------------
__global__ __launch_bounds__(256) void split_kernel(
    const float4* __restrict__ in, __nv_bfloat162* __restrict__ oh,
    __nv_bfloat162* __restrict__ ol, int n4)
{
    int i = blockIdx.x * blockDim.x + threadIdx.x;
    if (i >= n4) return;
    float4 v = in[i];
    __nv_bfloat16 h0, l0, h1, l1, h2, l2, h3, l3;
    split2(v.x, h0, l0); split2(v.y, h1, l1);
    split2(v.z, h2, l2); split2(v.w, h3, l3);
    __nv_bfloat162 a, b;
    a.x = h0; a.y = h1; b.x = h2; b.y = h3;
    oh[i * 2] = a; oh[i * 2 + 1] = b;
    a.x = l0; a.y = l1; b.x = l2; b.y = l3;
    ol[i * 2] = a; ol[i * 2 + 1] = b;
}

// ---------------------------------------------------------------------------
// Tensor-core projection: Y[b,o,n] = sum_c W[o,c] X[b,c,n] + bias[o]
// W pre-split bf16 hi/lo in global. X chunk double-buffered via cp.async.
// CTA: 64o x 128n. 256 thr (8 warps: 4 o-groups x 2 n-groups).
// smem: W 2x[64][72] + X 2buf x 2x[64][136] = 88 KB.
// ---------------------------------------------------------------------------
#define WLD 72
#define XLD 136

__global__ __launch_bounds__(256) void proj_mma_kernel(
    const __nv_bfloat16* __restrict__ Wh_g, const __nv_bfloat16* __restrict__ Wl_g,
    const float* __restrict__ bias,
    const __nv_bfloat16* __restrict__ Xh, const __nv_bfloat16* __restrict__ Xl,
    __nv_bfloat16* __restrict__ Yh, __nv_bfloat16* __restrict__ Yl,
    float* __restrict__ Yf, int R)
{
    extern __shared__ __nv_bfloat16 sp[];
    __nv_bfloat16* Wh   = sp;                    // [64][WLD]
    __nv_bfloat16* Wl   = Wh + 64 * WLD;
    __nv_bfloat16* Xbuf = Wl + 64 * WLD;         // [2][2][64*XLD]

    const int b  = blockIdx.z;
    const int o0 = blockIdx.y * 64;
    const int n0 = blockIdx.x * 128;
    const int tid  = threadIdx.x;
    const int warp = tid >> 5;
    const int lane = tid & 31;

    const __nv_bfloat16* Xbh = Xh + (size_t)b * CDIM * NN;
    const __nv_bfloat16* Xbl = Xl + (size_t)b * CDIM * NN;

    const uint32_t wh_b = cvta_s(Wh), wl_b = cvta_s(Wl);
    const uint32_t x_b  = cvta_s(Xbuf);
    const uint32_t xstride = 2u * 64 * XLD * 2;  // bytes per buf (h+l)

    // cp.async issue for X chunk kc into buffer `buf`
    auto issueX = [&](int kc, int buf) {
#pragma unroll
        for (int r = 0; r < 4; ++r) {
            int idx = tid + r * 256;
            int row = idx >> 4, c4 = idx & 15;
            uint32_t dh = x_b + buf * xstride + (uint32_t)(row * XLD + c4 * 8) * 2;
            cp16(dh, Xbh + (size_t)(kc * 64 + row) * NN + n0 + c4 * 8);
            cp16(dh + 64 * XLD * 2, Xbl + (size_t)(kc * 64 + row) * NN + n0 + c4 * 8);
        }
    };

    const int l7 = lane & 7, rr = lane >> 3;
    const int a_kofs = ((rr & 2) << 2) + l7;
    const int a_mofs = ((rr & 1) << 3);
    const int b_kofs = ((rr & 1) << 3) + l7;
    const int b_nofs = ((rr & 2) << 2);

    const int wo = warp >> 1;     // 4 o-groups of 16
    const int wn = warp & 1;      // 2 n-groups of 64

    float acc[8][4];
#pragma unroll
    for (int t = 0; t < 8; ++t)
#pragma unroll
        for (int e = 0; e < 4; ++e) acc[t][e] = 0.f;

    issueX(0, 0);
    cp_commit();

    for (int kc = 0; kc < 4; ++kc) {
        const int buf = kc & 1;
        // W chunk (64o x 64c) -> Ws[cc][o], bf16 direct (pre-split)
#pragma unroll
        for (int r = 0; r < 16; ++r) {
            int idx = tid + r * 256;
            int o = idx >> 6, cc = idx & 63;
            Wh[cc * WLD + o] = Wh_g[(size_t)(o0 + o) * CDIM + kc * 64 + cc];
            Wl[cc * WLD + o] = Wl_g[(size_t)(o0 + o) * CDIM + kc * 64 + cc];
        }
        if (kc < 3) {
            issueX(kc + 1, buf ^ 1);
            cp_commit();
            cp_wait<1>();
        } else {
            cp_wait<0>();
        }
        __syncthreads();

        const uint32_t xh_cur = x_b + buf * xstride;
        const uint32_t xl_cur = xh_cur + 64 * XLD * 2;

#pragma unroll
        for (int k0 = 0; k0 < 64; k0 += 16) {
            uint32_t ah[4], al[4];
            uint32_t aoff = (uint32_t)((k0 + a_kofs) * WLD + wo * 16 + a_mofs) * 2;
            ldsm_x4_t(ah, wh_b + aoff);
            ldsm_x4_t(al, wl_b + aoff);
#pragma unroll
            for (int jj = 0; jj < 4; ++jj) {
                uint32_t bh[4], bl[4];
                uint32_t boff =
                    (uint32_t)((k0 + b_kofs) * XLD + wn * 64 + jj * 16 + b_nofs) * 2;
                ldsm_x4_t(bh, xh_cur + boff);
                ldsm_x4_t(bl, xl_cur + boff);
                mma_bf16(acc[jj * 2 + 0], ah, bh + 0);
                mma_bf16(acc[jj * 2 + 0], ah, bl + 0);
                mma_bf16(acc[jj * 2 + 0], al, bh + 0);
                mma_bf16(acc[jj * 2 + 1], ah, bh + 2);
                mma_bf16(acc[jj * 2 + 1], ah, bl + 2);
                mma_bf16(acc[jj * 2 + 1], al, bh + 2);
            }
        }
        __syncthreads();
    }

    // epilogue: + bias, write split bf16 or fp32
    const int orow = wo * 16 + (lane >> 2);
    const float b0 = bias[o0 + orow];
    const float b1 = bias[o0 + orow + 8];
#pragma unroll
    for (int t = 0; t < 8; ++t) {
        int col = n0 + wn * 64 + t * 8 + (lane & 3) * 2;
        float v00 = acc[t][0] + b0, v01 = acc[t][1] + b0;
        float v10 = acc[t][2] + b1, v11 = acc[t][3] + b1;
        size_t i0 = ((size_t)b * R + o0 + orow) * NN + col;
        size_t i1 = ((size_t)b * R + o0 + orow + 8) * NN + col;
        if (Yf) {
            *(float2*)&Yf[i0] = make_float2(v00, v01);
            *(float2*)&Yf[i1] = make_float2(v10, v11);
        } else {
            __nv_bfloat16 h0, l0, h1, l1;
            __nv_bfloat162 th, tl;
            split2(v00, h0, l0); split2(v01, h1, l1);
            th.x = h0; th.y = h1; tl.x = l0; tl.y = l1;
            *(__nv_bfloat162*)&Yh[i0] = th;
            *(__nv_bfloat162*)&Yl[i0] = tl;
            split2(v10, h0, l0); split2(v11, h1, l1);
            th.x = h0; th.y = h1; tl.x = l0; tl.y = l1;
            *(__nv_bfloat162*)&Yh[i1] = th;
            *(__nv_bfloat162*)&Yl[i1] = tl;
        }
    }
}

// ---------------------------------------------------------------------------
// Fused attention, cp.async-pipelined. Per CTA: (b, 128 j). i tiled by 64.
// V(it) loads overlap the S-phase; Q(it+1) loads overlap the O-phase.
// ---------------------------------------------------------------------------
#define QLDb 72
#define KLDb 136
#define PLDb 136
#define VLDb 72

__global__ __launch_bounds__(512) void attn_bf16_kernel()
{
    extern __shared__ __nv_bfloat16 smb[];
    __nv_bfloat16* Qh = smb;                 // 64 x QLDb
    __nv_bfloat16* Ql = Qh + 64 * QLDb;
    __nv_bfloat16* Kh = Ql + 64 * QLDb;      // 64 x KLDb
    __nv_bfloat16* Kl = Kh + 64 * KLDb;
    __nv_bfloat16* Ph = Kl + 64 * KLDb;      // 64 x PLDb
    __nv_bfloat16* Pl = Ph + 64 * PLDb;
    __nv_bfloat16* Vh = Pl + 64 * PLDb;      // 256 x VLDb
    __nv_bfloat16* Vl = Vh + 256 * VLDb;

    const int b    = blockIdx.y;
    const int j0g  = blockIdx.x * 128;
    const int tid  = threadIdx.x;
    const int warp = tid >> 5;
    const int lane = tid & 31;

    const __nv_bfloat16* Qbh = g_Qh + (size_t)b * CKD * NN;
    const __nv_bfloat16* Qbl = g_Ql + (size_t)b * CKD * NN;
    const __nv_bfloat16* Kbh = g_Kh + (size_t)b * CKD * NN;
    const __nv_bfloat16* Kbl = g_Kl + (size_t)b * CKD * NN;
    const __nv_bfloat16* Vbh = g_Vh + (size_t)b * CDIM * NN;
    const __nv_bfloat16* Vbl = g_Vl + (size_t)b * CDIM * NN;

    const uint32_t qh_b = cvta_s(Qh), ql_b = cvta_s(Ql);
    const uint32_t kh_b = cvta_s(Kh), kl_b = cvta_s(Kl);
    const uint32_t ph_b = cvta_s(Ph), pl_b = cvta_s(Pl);
    const uint32_t vh_b = cvta_s(Vh), vl_b = cvta_s(Vl);

    // cp.async issuers
    auto issueQ = [&](int it) {
        int i0g = it * 64;
        int row = tid >> 3, c4 = tid & 7;
        uint32_t d = (uint32_t)(row * QLDb + c4 * 8) * 2;
        cp16(qh_b + d, Qbh + (size_t)row * NN + i0g + c4 * 8);
        cp16(ql_b + d, Qbl + (size_t)row * NN + i0g + c4 * 8);
    };
    auto issueV = [&](int it) {
        int i0g = it * 64;
#pragma unroll
        for (int r = 0; r < 4; ++r) {
            int idx = tid + r * 512;
            int row = idx >> 3, c4 = idx & 7;
            uint32_t d = (uint32_t)(row * VLDb + c4 * 8) * 2;
            cp16(vh_b + d, Vbh + (size_t)row * NN + i0g + c4 * 8);
            cp16(vl_b + d, Vbl + (size_t)row * NN + i0g + c4 * 8);
        }
    };

    // prologue: Q(0) async + K tile (regular loads)
    issueQ(0);
    cp_commit();
#pragma unroll
    for (int r = 0; r < 2; ++r) {
        int idx = tid + r * 512;
        int row = idx >> 4, c4 = idx & 15;
        *(uint4*)&Kh[row * KLDb + c4 * 8] =
            *(const uint4*)(Kbh + (size_t)row * NN + j0g + c4 * 8);
    }
#pragma unroll
    for (int r = 0; r < 2; ++r) {
        int idx = tid + r * 512;
        int row = idx >> 4, c4 = idx & 15;
        *(uint4*)&Kl[row * KLDb + c4 * 8] =
            *(const uint4*)(Kbl + (size_t)row * NN + j0g + c4 * 8);
    }
    cp_wait<0>();
    __syncthreads();

    // ldmatrix lane components (validated R4)
    const int l7 = lane & 7, rr = lane >> 3;
    const int a_dofs = ((rr & 2) << 2) + l7;
    const int a_iofs = ((rr & 1) << 3);
    const int b_kofs = ((rr & 1) << 3) + l7;
    const int b_jofs = ((rr & 2) << 2);
    const int v_row  = (lane & 15);
    const int v_col  = ((lane >> 4) << 3);

    const int s_i0 = (warp >> 2) * 16;            // S: 4 i-blocks
    const int s_jb = (warp & 3) * 32;             // S: 4 j-groups of 32
    const int o_c0 = (warp >> 1) * 32;            // O: 8 c-groups of 32
    const int o_j0 = (warp & 1) * 64;             // O: 2 j-groups of 64

    float oacc[16][4];
#pragma unroll
    for (int t = 0; t < 16; ++t)
#pragma unroll
        for (int e = 0; e < 4; ++e) oacc[t][e] = 0.f;

    for (int it = 0; it < 64; ++it) {
        // V(it) overlaps the S-phase
        issueV(it);
        cp_commit();

        // ---- S = Q^T K (warp: 16i x 32j) ----
        {
            float sacc[4][4];
#pragma unroll
            for (int t = 0; t < 4; ++t)
#pragma unroll
                for (int e = 0; e < 4; ++e) sacc[t][e] = 0.f;

#pragma unroll
            for (int k0 = 0; k0 < 64; k0 += 16) {
                uint32_t ah[4], al[4];
                uint32_t aoff = (uint32_t)((k0 + a_dofs) * QLDb + s_i0 + a_iofs) * 2;
                ldsm_x4_t(ah, qh_b + aoff);
                ldsm_x4_t(al, ql_b + aoff);
#pragma unroll
                for (int jj = 0; jj < 2; ++jj) {
                    int j0 = s_jb + jj * 16;
                    uint32_t bh[4], bl[4];
                    uint32_t boff = (uint32_t)((k0 + b_kofs) * KLDb + j0 + b_jofs) * 2;
                    ldsm_x4_t(bh, kh_b + boff);
                    ldsm_x4_t(bl, kl_b + boff);
                    mma_bf16(sacc[jj * 2 + 0], ah, bh + 0);
                    mma_bf16(sacc[jj * 2 + 0], ah, bl + 0);
                    mma_bf16(sacc[jj * 2 + 0], al, bh + 0);
                    mma_bf16(sacc[jj * 2 + 1], ah, bh + 2);
                    mma_bf16(sacc[jj * 2 + 1], ah, bl + 2);
                    mma_bf16(sacc[jj * 2 + 1], al, bh + 2);
                }
            }

            // P = elu(S)/N, split hi/lo to smem
            int prow = s_i0 + (lane >> 2);
            int pcol = (lane & 3) * 2;
#pragma unroll
            for (int t = 0; t < 4; ++t) {
                int jc = s_jb + t * 8 + pcol;
                float p0 = elu_scaled(sacc[t][0]);
                float p1 = elu_scaled(sacc[t][1]);
                float p2 = elu_scaled(sacc[t][2]);
                float p3 = elu_scaled(sacc[t][3]);
                __nv_bfloat16 h0, l0, h1, l1;
                __nv_bfloat162 th, tl;
                split2(p0, h0, l0); split2(p1, h1, l1);
                th.x = h0; th.y = h1; tl.x = l0; tl.y = l1;
                *(__nv_bfloat162*)&Ph[prow * PLDb + jc] = th;
                *(__nv_bfloat162*)&Pl[prow * PLDb + jc] = tl;
                split2(p2, h0, l0); split2(p3, h1, l1);
                th.x = h0; th.y = h1; tl.x = l0; tl.y = l1;
                *(__nv_bfloat162*)&Ph[(prow + 8) * PLDb + jc] = th;
                *(__nv_bfloat162*)&Pl[(prow + 8) * PLDb + jc] = tl;
            }
        }
        cp_wait<0>();        // V(it) arrived
        __syncthreads();     // P visible, Qs free

        // Q(it+1) overlaps the O-phase
        if (it < 63) {
            issueQ(it + 1);
            cp_commit();
        }

        // ---- O[c,j] += V P (warp: 32c x 64j) ----
#pragma unroll
        for (int k0 = 0; k0 < 64; k0 += 16) {
            uint32_t vh0[4], vl0[4], vh1[4], vl1[4];
            {
                uint32_t voff0 = (uint32_t)((o_c0 + v_row) * VLDb + k0 + v_col) * 2;
                uint32_t voff1 = (uint32_t)((o_c0 + 16 + v_row) * VLDb + k0 + v_col) * 2;
                ldsm_x4(vh0, vh_b + voff0);
                ldsm_x4(vl0, vl_b + voff0);
                ldsm_x4(vh1, vh_b + voff1);
                ldsm_x4(vl1, vl_b + voff1);
            }
#pragma unroll
            for (int jj = 0; jj < 4; ++jj) {
                uint32_t ph[4], pl[4];
                uint32_t boff =
                    (uint32_t)((k0 + b_kofs) * PLDb + o_j0 + jj * 16 + b_jofs) * 2;
                ldsm_x4_t(ph, ph_b + boff);
                ldsm_x4_t(pl, pl_b + boff);
                mma_bf16(oacc[jj * 2 + 0], vh0, ph + 0);
                mma_bf16(oacc[jj * 2 + 0], vh0, pl + 0);
                mma_bf16(oacc[jj * 2 + 0], vl0, ph + 0);
                mma_bf16(oacc[jj * 2 + 1], vh0, ph + 2);
                mma_bf16(oacc[jj * 2 + 1], vh0, pl + 2);
                mma_bf16(oacc[jj * 2 + 1], vl0, ph + 2);
                mma_bf16(oacc[8 + jj * 2 + 0], vh1, ph + 0);
                mma_bf16(oacc[8 + jj * 2 + 0], vh1, pl + 0);
                mma_bf16(oacc[8 + jj * 2 + 0], vl1, ph + 0);
                mma_bf16(oacc[8 + jj * 2 + 1], vh1, ph + 2);
                mma_bf16(oacc[8 + jj * 2 + 1], vh1, pl + 2);
                mma_bf16(oacc[8 + jj * 2 + 1], vl1, ph + 2);
            }
        }
        cp_wait<0>();        // Q(it+1) arrived
        __syncthreads();     // Vs/Ps free
    }

    // ---- store O accumulators, split bf16, to scratch ----
#pragma unroll
    for (int cb = 0; cb < 2; ++cb) {
        int orow = o_c0 + cb * 16 + (lane >> 2);
#pragma unroll
        for (int jj = 0; jj < 4; ++jj) {
#pragma unroll
            for (int h = 0; h < 2; ++h) {
                float* a = oacc[cb * 8 + jj * 2 + h];
                int col = j0g + o_j0 + jj * 16 + h * 8 + (lane & 3) * 2;
                size_t i0 = ((size_t)b * CDIM + orow) * NN + col;
                size_t i1 = ((size_t)b * CDIM + orow + 8) * NN + col;
                __nv_bfloat16 h0, l0, h1, l1;
                __nv_bfloat162 th, tl;
                split2(a[0], h0, l0); split2(a[1], h1, l1);
                th.x = h0; th.y = h1; tl.x = l0; tl.y = l1;
                *(__nv_bfloat162*)&g_Oh[i0] = th;
                *(__nv_bfloat162*)&g_Ol[i0] = tl;
                split2(a[2], h0, l0); split2(a[3], h1, l1);
                th.x = h0; th.y = h1; tl.x = l0; tl.y = l1;
                *(__nv_bfloat162*)&g_Oh[i1] = th;
                *(__nv_bfloat162*)&g_Ol[i1] = tl;
            }
        }
    }
}

// ---------------------------------------------------------------------------
extern "C" void kernel_launch(void* const* d_in, const int* in_sizes, int n_in,
                              void* d_out, int out_size)
{
    const float* x  = (const float*)d_in[0];
    const float* wq = (const float*)d_in[1];
    const float* bq = (const float*)d_in[2];
    const float* wk = (const float*)d_in[3];
    const float* bk = (const float*)d_in[4];
    const float* wv = (const float*)d_in[5];
    const float* bv = (const float*)d_in[6];
    const float* wg = (const float*)d_in[7];
    const float* bg = (const float*)d_in[8];
    float* out = (float*)d_out;

    __nv_bfloat16 *xh, *xl, *Qh, *Ql, *Kh, *Kl, *Vh, *Vl, *Oh, *Ol;
    __nv_bfloat16 *Wqh, *Wql, *Wkh, *Wkl, *Wvh, *Wvl, *Wgh, *Wgl;
    cudaGetSymbolAddress((void**)&xh, g_xh);
    cudaGetSymbolAddress((void**)&xl, g_xl);
    cudaGetSymbolAddress((void**)&Qh, g_Qh);
    cudaGetSymbolAddress((void**)&Ql, g_Ql);
    cudaGetSymbolAddress((void**)&Kh, g_Kh);
    cudaGetSymbolAddress((void**)&Kl, g_Kl);
    cudaGetSymbolAddress((void**)&Vh, g_Vh);
    cudaGetSymbolAddress((void**)&Vl, g_Vl);
    cudaGetSymbolAddress((void**)&Oh, g_Oh);
    cudaGetSymbolAddress((void**)&Ol, g_Ol);
    cudaGetSymbolAddress((void**)&Wqh, g_Wqh);
    cudaGetSymbolAddress((void**)&Wql, g_Wql);
    cudaGetSymbolAddress((void**)&Wkh, g_Wkh);
    cudaGetSymbolAddress((void**)&Wkl, g_Wkl);
    cudaGetSymbolAddress((void**)&Wvh, g_Wvh);
    cudaGetSymbolAddress((void**)&Wvl, g_Wvl);
    cudaGetSymbolAddress((void**)&Wgh, g_Wgh);
    cudaGetSymbolAddress((void**)&Wgl, g_Wgl);

    const int smem_attn =
        (2 * 64 * QLDb + 2 * 64 * KLDb + 2 * 64 * PLDb + 2 * 256 * VLDb) * 2;
    cudaFuncSetAttribute(attn_bf16_kernel, cudaFuncAttributeMaxDynamicSharedMemorySize,
                         smem_attn);
    const int smem_proj = (2 * 64 * WLD + 2 * 2 * 64 * XLD) * 2;
    cudaFuncSetAttribute(proj_mma_kernel, cudaFuncAttributeMaxDynamicSharedMemorySize,
                         smem_proj);

    // 1. split x and weights -> bf16 hi/lo
    const int n4x = NB * CDIM * NN / 4;
    split_kernel<<<(n4x + 255) / 256, 256>>>(
        (const float4*)x, (__nv_bfloat162*)xh, (__nv_bfloat162*)xl, n4x);
    const int n4s = CKD * CDIM / 4, n4b = CDIM * CDIM / 4;
    split_kernel<<<(n4s + 255) / 256, 256>>>(
        (const float4*)wq, (__nv_bfloat162*)Wqh, (__nv_bfloat162*)Wql, n4s);
    split_kernel<<<(n4s + 255) / 256, 256>>>(
        (const float4*)wk, (__nv_bfloat162*)Wkh, (__nv_bfloat162*)Wkl, n4s);
    split_kernel<<<(n4b + 255) / 256, 256>>>(
        (const float4*)wv, (__nv_bfloat162*)Wvh, (__nv_bfloat162*)Wvl, n4b);
    split_kernel<<<(n4b + 255) / 256, 256>>>(
        (const float4*)wg, (__nv_bfloat162*)Wgh, (__nv_bfloat162*)Wgl, n4b);

    // 2. QKV projections on tensor cores (split bf16 out)
    proj_mma_kernel<<<dim3(NN / 128, CKD / 64, NB), 256, smem_proj>>>(
        Wqh, Wql, bq, xh, xl, Qh, Ql, nullptr, CKD);
    proj_mma_kernel<<<dim3(NN / 128, CKD / 64, NB), 256, smem_proj>>>(
        Wkh, Wkl, bk, xh, xl, Kh, Kl, nullptr, CKD);
    proj_mma_kernel<<<dim3(NN / 128, CDIM / 64, NB), 256, smem_proj>>>(
        Wvh, Wvl, bv, xh, xl, Vh, Vl, nullptr, CDIM);

    // 3. Fused attention (energy never materialized), split bf16 out
    attn_bf16_kernel<<<dim3(NN / 128, NB), 512, smem_attn>>>();

    // 4. Final 1x1 conv (wg) -> fp32 output
    proj_mma_kernel<<<dim3(NN / 128, CDIM / 64, NB), 256, smem_proj>>>(
        Wgh, Wgl, bg, Oh, Ol, nullptr, nullptr, out, CDIM);
}